// round 4
// baseline (speedup 1.0000x reference)
#include <cuda_runtime.h>
#include <math.h>

#define BTOT 512
#define NMEM 30
#define HW 1024
#define NGTH_ 15
#define TPB 960

typedef unsigned long long u64;

__device__ __forceinline__ u64 dup2f(float v) {
    u64 r; asm("mov.b64 %0, {%1, %1};" : "=l"(r) : "f"(v)); return r;
}
__device__ __forceinline__ void fma2(u64& d, u64 a, u64 b) {
    asm("fma.rn.f32x2 %0, %1, %2, %0;" : "+l"(d) : "l"(a), "l"(b));
}
__device__ __forceinline__ float2 unp2(u64 v) {
    float lo, hi; asm("mov.b64 {%0, %1}, %2;" : "=f"(lo), "=f"(hi) : "l"(v));
    return make_float2(lo, hi);
}

__device__ float g_inp6[(size_t)BTOT * 6 * HW];
__device__ float g_cst[(size_t)BTOT * 8];

// ---------------------------------------------------------------------------
// Kernel 1: per-image statistics
// ---------------------------------------------------------------------------
__global__ __launch_bounds__(256) void stats_kernel(
    const float* __restrict__ ts,
    const float* __restrict__ ptm,
    const float* __restrict__ pmt,
    const float* __restrict__ piou,
    const void* __restrict__ mask_raw)
{
    const int b = blockIdx.x;
    const int tid = threadIdx.x;
    const int lane = tid & 31;
    const int wid = tid >> 5;

    __shared__ float mf[NMEM], ow[NMEM];
    __shared__ float pmax[NMEM];
    __shared__ float warpmax[8];
    __shared__ float sc[16];

    unsigned int w0 = *(const unsigned int*)mask_raw;
    int mode = (w0 == 1u) ? 1 : ((w0 == 0x3F800000u) ? 2 : 0);

    if (tid == 0) {
        float run = 0.f, ca = 0.f, cg = 0.f, co = 0.f;
        for (int m = 0; m < NMEM; ++m) {
            int idx = b * NMEM + m;
            float f;
            if (mode == 1)      f = (((const int*)mask_raw)[idx] != 0) ? 1.f : 0.f;
            else if (mode == 2) f = (((const float*)mask_raw)[idx] != 0.f) ? 1.f : 0.f;
            else                f = (((const unsigned char*)mask_raw)[idx] != 0) ? 1.f : 0.f;
            run += f;
            float rank = run - 1.f;
            float g = (rank < (float)NGTH_) ? f : 0.f;
            float o = f - g;
            mf[m] = f; ow[m] = o;
            ca += f; cg += g; co += o;
        }
        sc[7] = ca; sc[8] = cg; sc[9] = co;
    }

    float tmax = -INFINITY;
    const float* tsb = ts + (size_t)b * HW;
    for (int p = tid; p < HW; p += 256) tmax = fmaxf(tmax, tsb[p]);
    #pragma unroll
    for (int off = 16; off > 0; off >>= 1)
        tmax = fmaxf(tmax, __shfl_xor_sync(0xffffffffu, tmax, off));
    if (lane == 0) warpmax[wid] = tmax;

    const float* ptmb = ptm + (size_t)b * NMEM * HW;
    for (int m = wid; m < NMEM; m += 8) {
        float mx = -INFINITY;
        const float* pr = ptmb + (size_t)m * HW;
        for (int p = lane; p < HW; p += 32) mx = fmaxf(mx, pr[p]);
        #pragma unroll
        for (int off = 16; off > 0; off >>= 1)
            mx = fmaxf(mx, __shfl_xor_sync(0xffffffffu, mx, off));
        if (lane == 0) pmax[m] = mx;
    }
    __syncthreads();

    if (wid == 0) {
        float v = (lane < 8) ? warpmax[lane] : -INFINITY;
        #pragma unroll
        for (int off = 4; off > 0; off >>= 1)
            v = fmaxf(v, __shfl_xor_sync(0xffffffffu, v, off));
        if (lane == 0) sc[0] = v;
    }
    if (wid == 1) {
        float v  = (lane < NMEM) ? pmax[lane] : 0.f;
        float fa = (lane < NMEM) ? mf[lane] : 0.f;
        float fo = (lane < NMEM) ? ow[lane] : 0.f;
        float fg = fa - fo;
        float sa = v * fa, ssa = v * v * fa;
        float sg = v * fg, ssg = v * v * fg;
        float so = v * fo, sso = v * v * fo;
        #pragma unroll
        for (int off = 16; off > 0; off >>= 1) {
            sa  += __shfl_xor_sync(0xffffffffu, sa, off);
            ssa += __shfl_xor_sync(0xffffffffu, ssa, off);
            sg  += __shfl_xor_sync(0xffffffffu, sg, off);
            ssg += __shfl_xor_sync(0xffffffffu, ssg, off);
            so  += __shfl_xor_sync(0xffffffffu, so, off);
            sso += __shfl_xor_sync(0xffffffffu, sso, off);
        }
        if (lane == 0) {
            float ca = sc[7], cg = sc[8], co = sc[9];
            float mA = sa / ca; sc[1] = mA; sc[2] = sqrtf(fmaxf(ssa / ca - mA * mA, 0.f));
            float mG = sg / cg; sc[3] = mG; sc[4] = sqrtf(fmaxf(ssg / cg - mG * mG, 0.f));
            float mO = so / co; sc[5] = mO; sc[6] = sqrtf(fmaxf(sso / co - mO * mO, 0.f));
        }
    }
    __syncthreads();

    if (tid == 0) {
        float* c = g_cst + (size_t)b * 8;
        c[0] = sc[0]; c[1] = piou[b];
        c[2] = sc[1]; c[3] = sc[2]; c[4] = sc[3];
        c[5] = sc[4]; c[6] = sc[5]; c[7] = sc[6];
    }

    float* ob = g_inp6 + (size_t)b * 6 * HW;
    const float* pmtb = pmt + (size_t)b * NMEM * HW;
    const float ca = sc[7], co = sc[9];

    for (int p = tid; p < HW; p += 256) {
        float sa = 0, ssa = 0, sg = 0, ssg = 0, so = 0, sso = 0;
        #pragma unroll 5
        for (int m = 0; m < NMEM; ++m) {
            float v = pmtb[(size_t)m * HW + p];
            float fa = mf[m], fo = ow[m];
            sa += v * fa; ssa += v * v * fa;
            if (m < NGTH_) { sg += v; ssg += v * v; }
            so += v * fo; sso += v * v * fo;
        }
        float mA = sa / ca, sA = sqrtf(fmaxf(ssa / ca - mA * mA, 0.f));
        float mG = sg * (1.f / NGTH_), sG = sqrtf(fmaxf(ssg * (1.f / NGTH_) - mG * mG, 0.f));
        float mO = so / co, sO = sqrtf(fmaxf(sso / co - mO * mO, 0.f));
        ob[0 * HW + p] = mA;
        ob[1 * HW + p] = sA;
        ob[2 * HW + p] = mG;
        ob[3 * HW + p] = sG;
        ob[4 * HW + p] = mO;
        ob[5 * HW + p] = sO;
    }
}

// ---------------------------------------------------------------------------
// Fused CNN. 30 warps/CTA, 1-ocpair items.
// smem float layout (stride 18 tiles, input stride 34):
//   OA  [0,     14976)  conv1 input 6x32x34=6528 / x2 64x13x18=14976
//   OB  [14976, 32256)  x1 64x15x18=17280        / x3 64x11x18=12672
//   OWT [32256, 50688)  weights (32 ocp x 32 ic x 18)
//   OE  [50688, 50816)  folded BN scale[64]+bias[64]
//   ORED[50816, 50848)
// ---------------------------------------------------------------------------
#define OA 0
#define OB 14976
#define OWT 32256
#define OE 50688
#define ORED 50816
#define SMEM_FLOATS 50848
#define SMEM_BYTES (SMEM_FLOATS * 4)
#define S_T 18

// 64->64 3x3 conv stage; item = 1 oc-pair x 1 row x BLKW cols (x0 = blk*6).
template<int INCS, int OUTCS, int NR, int NCV, int BLKW, int DW, bool OVL>
__device__ __forceinline__ void conv64_stage(
    float* sm, int inOff, int outOff,
    const float* __restrict__ wsrc,
    const float* __restrict__ cbv, const float* __restrict__ gv,
    const float* __restrict__ bbv, const float* __restrict__ mv,
    const float* __restrict__ vv)
{
    const int tid = threadIdx.x;
    const int NITEMS = 32 * NR * 2;
    const bool act = tid < NITEMS;
    int ocp = 0, row = 0, blk = 0;
    if (act) {
        ocp = tid / (NR * 2);
        int r = tid - ocp * (NR * 2);
        row = r % NR;
        blk = r / NR;
    }
    const int x0 = blk * 6;

    u64 acc[BLKW];
    #pragma unroll
    for (int c = 0; c < BLKW; ++c) acc[c] = 0ull;

    for (int h = 0; h < 2; ++h) {
        __syncthreads();
        for (int i = tid; i < 64 * 32 * 9; i += TPB) {
            int oc = i / 288; int r = i - oc * 288;
            int icl = r / 9; int t = r - icl * 9;
            sm[OWT + ((oc >> 1) * 32 + icl) * 18 + t * 2 + (oc & 1)] =
                wsrc[oc * 576 + h * 288 + r];
        }
        if (h == 0 && tid < 64) {
            float s = gv[tid] * rsqrtf(vv[tid] + 1e-5f);
            sm[OE + tid] = s;
            sm[OE + 64 + tid] = s * (cbv[tid] - mv[tid]) + bbv[tid];
        }
        __syncthreads();

        if (act) {
            const float* ibase = &sm[inOff + h * 32 * INCS + row * S_T + x0];
            for (int icl = 0; icl < 32; ++icl) {
                const float* ib = ibase + icl * INCS;
                const u64* wb = (const u64*)&sm[OWT + (ocp * 32 + icl) * 18];
                #pragma unroll
                for (int ky = 0; ky < 3; ++ky) {
                    u64 d[DW];
                    #pragma unroll
                    for (int q = 0; q < DW / 2; ++q) {
                        float2 a = *(const float2*)(ib + ky * S_T + 2 * q);
                        d[2 * q] = dup2f(a.x); d[2 * q + 1] = dup2f(a.y);
                    }
                    #pragma unroll
                    for (int kx = 0; kx < 3; ++kx) {
                        u64 w = wb[ky * 3 + kx];
                        #pragma unroll
                        for (int c = 0; c < BLKW; ++c)
                            fma2(acc[c], w, d[c + kx]);
                    }
                }
            }
        }
    }

    if (act) {
        int oc0 = 2 * ocp;
        float s0 = sm[OE + oc0],     bi0 = sm[OE + 64 + oc0];
        float s1 = sm[OE + oc0 + 1], bi1 = sm[OE + 64 + oc0 + 1];
        #pragma unroll
        for (int c = 0; c < BLKW; ++c) {
            int x = x0 + c;
            bool wr = (x < NCV) && !(OVL && blk == 1 && c == 0);
            if (wr) {
                float2 v = unp2(acc[c]);
                sm[outOff + oc0 * OUTCS + row * S_T + x] = fmaxf(s0 * v.x + bi0, 0.f);
                sm[outOff + (oc0 + 1) * OUTCS + row * S_T + x] = fmaxf(s1 * v.y + bi1, 0.f);
            }
        }
    }
}

__global__ __launch_bounds__(TPB, 1) void cnn_kernel(
    const float* __restrict__ w1, const float* __restrict__ cb1,
    const float* __restrict__ g1, const float* __restrict__ bb1,
    const float* __restrict__ m1, const float* __restrict__ v1,
    const float* __restrict__ w2, const float* __restrict__ cb2,
    const float* __restrict__ g2, const float* __restrict__ bb2,
    const float* __restrict__ m2, const float* __restrict__ v2,
    const float* __restrict__ w3, const float* __restrict__ cb3,
    const float* __restrict__ g3, const float* __restrict__ bb3,
    const float* __restrict__ m3, const float* __restrict__ v3,
    const float* __restrict__ w4, const float* __restrict__ cb4,
    float* __restrict__ out)
{
    extern __shared__ float sm[];
    const int b = blockIdx.x;
    const int tid = threadIdx.x;

    // ---------------- prologue: input (stride 34), conv1 weights, E1 ----------------
    {
        const float* src = g_inp6 + (size_t)b * 6 * HW;
        for (int i = tid; i < 6 * HW; i += TPB) {
            int c = i >> 10; int rem = i & 1023;
            int r = rem >> 5; int x = rem & 31;
            sm[OA + c * 1088 + r * 34 + x] = src[i];
        }
        for (int i = tid; i < 64 * 6 * 9; i += TPB) {
            int oc = i / 54; int r = i - oc * 54;
            int c = r / 9; int t = r - c * 9;
            sm[OWT + ((oc >> 1) * 6 + c) * 18 + t * 2 + (oc & 1)] =
                w1[oc * 126 + (c + 2) * 9 + t];
        }
        if (tid < 64) {
            const float* cst = g_cst + (size_t)b * 8;
            float extra = 0.f;
            #pragma unroll
            for (int j = 0; j < 8; ++j) {
                int ic = (j < 2) ? j : (j + 6);
                const float* wb = w1 + tid * 126 + ic * 9;
                float s9 = 0.f;
                #pragma unroll
                for (int t = 0; t < 9; ++t) s9 += wb[t];
                extra += cst[j] * s9;
            }
            float s = g1[tid] * rsqrtf(v1[tid] + 1e-5f);
            sm[OE + tid] = s;
            sm[OE + 64 + tid] = s * (extra + cb1[tid] - m1[tid]) + bb1[tid];
        }
    }
    __syncthreads();

    // ---------------- stage 1: conv1 (6ic) + bn + relu + 2x2 pool -> x1 (OB) ----------------
    // item = 1 ocp x 1 pooled row x 2 pooled cols; 32*15*8 = 3840 items = 4 exact rounds
    #pragma unroll
    for (int itb = 0; itb < 4; ++itb) {
        int it = tid + itb * TPB;
        int ocp = it / 120;
        int r = it - ocp * 120;
        int pr = r >> 3;
        int pq = r & 7;
        int x0 = 4 * pq, r0 = 2 * pr;

        u64 acc[2][4];
        #pragma unroll
        for (int e = 0; e < 2; ++e)
            #pragma unroll
            for (int c = 0; c < 4; ++c) acc[e][c] = 0ull;

        for (int ch = 0; ch < 6; ++ch) {
            const float* ib = &sm[OA + ch * 1088 + r0 * 34 + x0];
            const u64* wb = (const u64*)&sm[OWT + (ocp * 6 + ch) * 18];
            #pragma unroll
            for (int ir = 0; ir < 4; ++ir) {
                u64 d[6];
                #pragma unroll
                for (int q = 0; q < 3; ++q) {
                    float2 a = *(const float2*)(ib + ir * 34 + 2 * q);
                    d[2 * q] = dup2f(a.x); d[2 * q + 1] = dup2f(a.y);
                }
                #pragma unroll
                for (int kx = 0; kx < 3; ++kx) {
                    if (ir <= 2) {
                        u64 w = wb[ir * 3 + kx];
                        #pragma unroll
                        for (int c = 0; c < 4; ++c) fma2(acc[0][c], w, d[c + kx]);
                    }
                    if (ir >= 1) {
                        u64 w = wb[(ir - 1) * 3 + kx];
                        #pragma unroll
                        for (int c = 0; c < 4; ++c) fma2(acc[1][c], w, d[c + kx]);
                    }
                }
            }
        }
        {
            int oc0 = 2 * ocp;
            float s0 = sm[OE + oc0],     bi0 = sm[OE + 64 + oc0];
            float s1 = sm[OE + oc0 + 1], bi1 = sm[OE + 64 + oc0 + 1];
            #pragma unroll
            for (int j = 0; j < 2; ++j) {
                int pt = 2 * pq + j;
                if (pt < 15) {
                    float2 a = unp2(acc[0][2 * j]);
                    float2 bq = unp2(acc[0][2 * j + 1]);
                    float2 cq = unp2(acc[1][2 * j]);
                    float2 e = unp2(acc[1][2 * j + 1]);
                    float lo = fmaxf(fmaxf(fmaxf(s0 * a.x + bi0, 0.f), fmaxf(s0 * bq.x + bi0, 0.f)),
                                     fmaxf(fmaxf(s0 * cq.x + bi0, 0.f), fmaxf(s0 * e.x + bi0, 0.f)));
                    float hi = fmaxf(fmaxf(fmaxf(s1 * a.y + bi1, 0.f), fmaxf(s1 * bq.y + bi1, 0.f)),
                                     fmaxf(fmaxf(s1 * cq.y + bi1, 0.f), fmaxf(s1 * e.y + bi1, 0.f)));
                    sm[OB + oc0 * 270 + pr * S_T + pt] = lo;
                    sm[OB + (oc0 + 1) * 270 + pr * S_T + pt] = hi;
                }
            }
        }
    }

    // ---------------- stage 2: conv2 (15x15 -> 13x13), OB -> OA ----------------
    conv64_stage<270, 234, 13, 13, 7, 10, true>(sm, OB, OA, w2, cb2, g2, bb2, m2, v2);

    // ---------------- stage 3: conv3 (13x13 -> 11x11), OA -> OB ----------------
    conv64_stage<234, 198, 11, 11, 6, 8, false>(sm, OA, OB, w3, cb3, g3, bb3, m3, v3);

    // ---------------- stage 4: conv4 (64->1, 11x11 -> 9x9) + global max ----------------
    __syncthreads();
    for (int i = tid; i < 576; i += TPB) sm[OWT + i] = w4[i];
    __syncthreads();

    float lmax = -INFINITY;
    if (tid < 81) {
        int y = tid / 9, x = tid - (tid / 9) * 9;
        float a = 0.f;
        for (int ic = 0; ic < 64; ++ic) {
            const float* ib = &sm[OB + ic * 198 + y * S_T + x];
            const float* wb = &sm[OWT + ic * 9];
            #pragma unroll
            for (int ky = 0; ky < 3; ++ky)
                #pragma unroll
                for (int kx = 0; kx < 3; ++kx)
                    a += ib[ky * S_T + kx] * wb[ky * 3 + kx];
        }
        lmax = a;
    }
    #pragma unroll
    for (int off = 16; off > 0; off >>= 1)
        lmax = fmaxf(lmax, __shfl_xor_sync(0xffffffffu, lmax, off));
    if ((tid & 31) == 0) sm[ORED + (tid >> 5)] = lmax;
    __syncthreads();
    if (tid < 32) {
        float v = (tid < TPB / 32) ? sm[ORED + tid] : -INFINITY;
        #pragma unroll
        for (int off = 16; off > 0; off >>= 1)
            v = fmaxf(v, __shfl_xor_sync(0xffffffffu, v, off));
        if (tid == 0) out[b] = v + cb4[0];
    }
}

// ---------------------------------------------------------------------------
extern "C" void kernel_launch(void* const* d_in, const int* in_sizes, int n_in,
                              void* d_out, int out_size)
{
    cudaFuncSetAttribute(cnn_kernel, cudaFuncAttributeMaxDynamicSharedMemorySize, SMEM_BYTES);

    stats_kernel<<<BTOT, 256>>>(
        (const float*)d_in[0],   // target_scores
        (const float*)d_in[1],   // ptm
        (const float*)d_in[2],   // pmt
        (const float*)d_in[3],   // predicted_iou
        d_in[4]);                // mem_mask (dtype auto-detected)

    cnn_kernel<<<BTOT, TPB, SMEM_BYTES>>>(
        (const float*)d_in[5],  (const float*)d_in[6],
        (const float*)d_in[7],  (const float*)d_in[8],
        (const float*)d_in[9],  (const float*)d_in[10],
        (const float*)d_in[11], (const float*)d_in[12],
        (const float*)d_in[13], (const float*)d_in[14],
        (const float*)d_in[15], (const float*)d_in[16],
        (const float*)d_in[17], (const float*)d_in[18],
        (const float*)d_in[19], (const float*)d_in[20],
        (const float*)d_in[21], (const float*)d_in[22],
        (const float*)d_in[23], (const float*)d_in[24],
        (float*)d_out);
}